// round 6
// baseline (speedup 1.0000x reference)
#include <cuda_runtime.h>
#include <math.h>

#define BB   4
#define CC   128
#define TT   1000
#define FF   128
#define NHD  4
#define HID  16
#define VD   32
#define EQ   2048
#define EV   4096
#define EPSL 1e-5f

// ---------------- scratch (device globals; no allocation) ----------------
__device__ float g_Q[(size_t)NHD*BB*TT*EQ];   // [hb][t][e]
__device__ float g_K[(size_t)NHD*BB*TT*EQ];
__device__ float g_V[(size_t)NHD*BB*TT*EV];
__device__ float g_S[(size_t)NHD*BB*TT*TT];   // scores -> probs
__device__ float g_O[(size_t)NHD*BB*TT*EV];   // attention output

// packed fp32x2 FMA: d = a*b + d  (FFMA2: 2x fp32 throughput, PTX-only path)
__device__ __forceinline__ void ffma2(float2 &d, float2 a, float2 b) {
    asm("fma.rn.f32x2 %0, %1, %2, %0;"
        : "+l"(reinterpret_cast<unsigned long long&>(d))
        : "l"(reinterpret_cast<unsigned long long&>(a)),
          "l"(reinterpret_cast<unsigned long long&>(b)));
}

// =========================================================================
// Kernel 1: fused QKV 1x1-conv GEMM + bias + PReLU + group LayerNorm
// grid (T, B), 256 threads. Out channels: [Q 0..63 | K 64..127 | V 128..255]
// =========================================================================
#define SMEM_A ((128*132 + 128*256)*4)
__global__ void __launch_bounds__(256, 1) qkv_kernel(
    const float* __restrict__ x,
    const float* __restrict__ Wq, const float* __restrict__ bq,
    const float* __restrict__ aq, const float* __restrict__ gq, const float* __restrict__ beq,
    const float* __restrict__ Wk, const float* __restrict__ bk,
    const float* __restrict__ ak, const float* __restrict__ gk, const float* __restrict__ bek,
    const float* __restrict__ Wv, const float* __restrict__ bv,
    const float* __restrict__ av, const float* __restrict__ gv, const float* __restrict__ bev)
{
    const int t = blockIdx.x, b = blockIdx.y;
    const int tid = threadIdx.x, ty = tid >> 4, tx = tid & 15;
    extern __shared__ float sm[];
    float* Xs = sm;             // [128 c][132 f-padded]
    float* Ws = sm + 128*132;   // [128 c][256 oc]
    __shared__ float ssum[256], ssq[256], gmu[12], grs[12];

    // stage X[b, :, t, :]
    {
        int c = tid >> 1, hh = (tid & 1) * 64;
        const float4* src = (const float4*)(x + (((size_t)b*CC + c)*TT + t)*FF + hh);
        float4* dst = (float4*)(Xs + c*132 + hh);
        #pragma unroll
        for (int i = 0; i < 16; i++) dst[i] = src[i];
    }
    // stage combined W, c-major
    {
        const float* wrow = (tid < 64)  ? (Wq + tid*CC)
                          : (tid < 128) ? (Wk + (tid-64)*CC)
                          :               (Wv + (tid-128)*CC);
        const float4* w4 = (const float4*)wrow;
        #pragma unroll
        for (int c4 = 0; c4 < 32; c4++) {
            float4 v = w4[c4];
            int c = c4*4;
            Ws[(c+0)*256 + tid] = v.x;
            Ws[(c+1)*256 + tid] = v.y;
            Ws[(c+2)*256 + tid] = v.z;
            Ws[(c+3)*256 + tid] = v.w;
        }
    }
    __syncthreads();

    // microtile: 16 oc (ty*16..+15, as 8 pairs) x 8 f (tx*4..+3, 64+tx*4..+3)
    float2 acc[8][8];
    #pragma unroll
    for (int p = 0; p < 8; p++)
        #pragma unroll
        for (int f = 0; f < 8; f++) acc[p][f] = make_float2(0.f, 0.f);

    for (int c = 0; c < 128; c++) {
        const float* xr = Xs + c*132;
        float4 xa = *(const float4*)(xr + tx*4);
        float4 xb = *(const float4*)(xr + 64 + tx*4);
        const float4* wr = (const float4*)(Ws + c*256) + ty*4;
        float4 w0 = wr[0], w1 = wr[1], w2 = wr[2], w3 = wr[3];
        float2 wp2[8] = {{w0.x,w0.y},{w0.z,w0.w},{w1.x,w1.y},{w1.z,w1.w},
                         {w2.x,w2.y},{w2.z,w2.w},{w3.x,w3.y},{w3.z,w3.w}};
        float xv[8] = {xa.x,xa.y,xa.z,xa.w,xb.x,xb.y,xb.z,xb.w};
        #pragma unroll
        for (int f = 0; f < 8; f++) {
            float2 xx = make_float2(xv[f], xv[f]);
            #pragma unroll
            for (int p = 0; p < 8; p++) ffma2(acc[p][f], wp2[p], xx);
        }
    }

    // bias + PReLU + local sums
    float alpha = (ty < 4) ? aq[ty] : (ty < 8) ? ak[ty-4] : av[(ty-8)>>1];
    int grp = (ty < 8) ? ty : 8 + ((ty-8)>>1);
    float s1 = 0.f, s2 = 0.f;
    #pragma unroll
    for (int p = 0; p < 8; p++) {
        int occ = ty*16 + 2*p;
        float b0 = (occ < 64) ? bq[occ]   : (occ < 128) ? bk[occ-64] : bv[occ-128];
        float b1 = (occ < 64) ? bq[occ+1] : (occ < 128) ? bk[occ-63] : bv[occ-127];
        #pragma unroll
        for (int f = 0; f < 8; f++) {
            float vx = acc[p][f].x + b0; vx = vx >= 0.f ? vx : alpha*vx;
            float vy = acc[p][f].y + b1; vy = vy >= 0.f ? vy : alpha*vy;
            acc[p][f].x = vx; acc[p][f].y = vy;
            s1 += vx + vy; s2 += vx*vx + vy*vy;
        }
    }
    ssum[tid] = s1; ssq[tid] = s2;
    __syncthreads();
    // 12 LN groups map to contiguous tid ranges
    if (tid < 12) {
        int st = (tid < 8) ? tid*16 : 128 + (tid-8)*32;
        int n  = (tid < 8) ? 16 : 32;
        float a = 0.f, q = 0.f;
        for (int i = 0; i < n; i++) { a += ssum[st+i]; q += ssq[st+i]; }
        float N = (tid < 8) ? 2048.f : 4096.f;
        float mu = a / N;
        float var = q / N - mu*mu;
        gmu[tid] = mu;
        grs[tid] = rsqrtf(var + EPSL);
    }
    __syncthreads();
    float mu = gmu[grp], rs = grs[grp];

    // normalize + affine, write in attention layout [hb][t][e]
    #pragma unroll
    for (int p = 0; p < 8; p++) {
        #pragma unroll
        for (int lane = 0; lane < 2; lane++) {
            int occ = ty*16 + 2*p + lane;
            const float* grow; const float* berow; float* dst;
            if (occ < 64) {
                grow = gq + occ*FF; berow = beq + occ*FF;
                int h = occ >> 4, r = occ & 15;
                dst = g_Q + (((size_t)(h*BB + b))*TT + t)*EQ + r*FF;
            } else if (occ < 128) {
                int o2 = occ - 64;
                grow = gk + o2*FF; berow = bek + o2*FF;
                int h = o2 >> 4, r = o2 & 15;
                dst = g_K + (((size_t)(h*BB + b))*TT + t)*EQ + r*FF;
            } else {
                int o2 = occ - 128;
                grow = gv + o2*FF; berow = bev + o2*FF;
                int h = o2 >> 5, r = o2 & 31;
                dst = g_V + (((size_t)(h*BB + b))*TT + t)*EV + r*FF;
            }
            #pragma unroll
            for (int half = 0; half < 2; half++) {
                int fc = half*64 + tx*4;
                float4 g4  = *(const float4*)(grow + fc);
                float4 be4 = *(const float4*)(berow + fc);
                float v0 = lane ? acc[p][half*4+0].y : acc[p][half*4+0].x;
                float v1 = lane ? acc[p][half*4+1].y : acc[p][half*4+1].x;
                float v2 = lane ? acc[p][half*4+2].y : acc[p][half*4+2].x;
                float v3 = lane ? acc[p][half*4+3].y : acc[p][half*4+3].x;
                float4 o;
                o.x = (v0 - mu)*rs*g4.x + be4.x;
                o.y = (v1 - mu)*rs*g4.y + be4.y;
                o.z = (v2 - mu)*rs*g4.z + be4.z;
                o.w = (v3 - mu)*rs*g4.w + be4.w;
                *(float4*)(dst + fc) = o;
            }
        }
    }
}

// =========================================================================
// Kernel 2: S = Q K^T * scale, lower-triangular tiles only, double-buffered
// grid (36, 1, 16), 256 thr, 128x128 tile, k=2048
// =========================================================================
__global__ void __launch_bounds__(256) score_kernel()
{
    // map linear tile id -> (tt, ss) with ss <= tt
    int idx = blockIdx.x;
    int tt = (int)((sqrtf(8.f*idx + 1.f) - 1.f) * 0.5f);
    while ((tt+1)*(tt+2)/2 <= idx) tt++;
    while (tt*(tt+1)/2 > idx) tt--;
    const int ss = idx - tt*(tt+1)/2;
    const int hb = blockIdx.z;
    const int t0 = tt*128, s0 = ss*128;
    const int tid = threadIdx.x, ty = tid >> 4, tx = tid & 15;
    __shared__ float Qs[2][16*132], Ks[2][16*132];

    float2 acc[8][4];
    #pragma unroll
    for (int i = 0; i < 8; i++)
        #pragma unroll
        for (int j = 0; j < 4; j++) acc[i][j] = make_float2(0.f, 0.f);

    const float* Qb = g_Q + (size_t)hb*TT*EQ;
    const float* Kb = g_K + (size_t)hb*TT*EQ;
    const int r = tid >> 2, q4 = (tid & 3)*4;

    float4 vq[2], vk[2];
    // prologue: load slab 0
    #pragma unroll
    for (int pass = 0; pass < 2; pass++) {
        int rr = r + pass*64;
        int tg = t0 + rr, sg = s0 + rr;
        vq[pass] = (tg < TT) ? *(const float4*)(Qb + (size_t)tg*EQ + q4)
                             : make_float4(0.f,0.f,0.f,0.f);
        vk[pass] = (sg < TT) ? *(const float4*)(Kb + (size_t)sg*EQ + q4)
                             : make_float4(0.f,0.f,0.f,0.f);
    }
    #pragma unroll
    for (int pass = 0; pass < 2; pass++) {
        int rr = r + pass*64;
        Qs[0][(q4+0)*132+rr]=vq[pass].x; Qs[0][(q4+1)*132+rr]=vq[pass].y;
        Qs[0][(q4+2)*132+rr]=vq[pass].z; Qs[0][(q4+3)*132+rr]=vq[pass].w;
        Ks[0][(q4+0)*132+rr]=vk[pass].x; Ks[0][(q4+1)*132+rr]=vk[pass].y;
        Ks[0][(q4+2)*132+rr]=vk[pass].z; Ks[0][(q4+3)*132+rr]=vk[pass].w;
    }
    __syncthreads();

    const int NSLAB = EQ/16;  // 128
    for (int it = 0; it < NSLAB; it++) {
        const int cur = it & 1;
        // issue next slab's global loads before compute (latency overlap)
        if (it + 1 < NSLAB) {
            int e0 = (it+1)*16;
            #pragma unroll
            for (int pass = 0; pass < 2; pass++) {
                int rr = r + pass*64;
                int tg = t0 + rr, sg = s0 + rr;
                vq[pass] = (tg < TT) ? *(const float4*)(Qb + (size_t)tg*EQ + e0 + q4)
                                     : make_float4(0.f,0.f,0.f,0.f);
                vk[pass] = (sg < TT) ? *(const float4*)(Kb + (size_t)sg*EQ + e0 + q4)
                                     : make_float4(0.f,0.f,0.f,0.f);
            }
        }
        const float* qsb = Qs[cur];
        const float* ksb = Ks[cur];
        #pragma unroll
        for (int kk = 0; kk < 16; kk++) {
            float4 q0 = *(const float4*)(qsb + kk*132 + ty*4);
            float4 q1 = *(const float4*)(qsb + kk*132 + 64 + ty*4);
            float4 k0 = *(const float4*)(ksb + kk*132 + tx*4);
            float4 k1 = *(const float4*)(ksb + kk*132 + 64 + tx*4);
            float2 cp[4] = {{k0.x,k0.y},{k0.z,k0.w},{k1.x,k1.y},{k1.z,k1.w}};
            float qv[8] = {q0.x,q0.y,q0.z,q0.w,q1.x,q1.y,q1.z,q1.w};
            #pragma unroll
            for (int i = 0; i < 8; i++) {
                float2 qq = make_float2(qv[i], qv[i]);
                #pragma unroll
                for (int j = 0; j < 4; j++) ffma2(acc[i][j], qq, cp[j]);
            }
        }
        if (it + 1 < NSLAB) {
            const int nxt = cur ^ 1;
            #pragma unroll
            for (int pass = 0; pass < 2; pass++) {
                int rr = r + pass*64;
                Qs[nxt][(q4+0)*132+rr]=vq[pass].x; Qs[nxt][(q4+1)*132+rr]=vq[pass].y;
                Qs[nxt][(q4+2)*132+rr]=vq[pass].z; Qs[nxt][(q4+3)*132+rr]=vq[pass].w;
                Ks[nxt][(q4+0)*132+rr]=vk[pass].x; Ks[nxt][(q4+1)*132+rr]=vk[pass].y;
                Ks[nxt][(q4+2)*132+rr]=vk[pass].z; Ks[nxt][(q4+3)*132+rr]=vk[pass].w;
            }
            __syncthreads();
        }
    }

    const float scale = 0.022097086912079608f;  // 1/sqrt(2048)
    float* Sb = g_S + (size_t)hb*TT*TT;
    #pragma unroll
    for (int i = 0; i < 8; i++) {
        int trow = t0 + ((i < 4) ? ty*4 + i : 64 + ty*4 + (i-4));
        if (trow >= TT) continue;
        float* srow = Sb + (size_t)trow*TT;
        #pragma unroll
        for (int j = 0; j < 4; j++) {
            int scol = s0 + ((j < 2) ? tx*4 + 2*j : 64 + tx*4 + 2*(j-2));
            if (scol   <= trow && scol   < TT) srow[scol]   = acc[i][j].x * scale;
            if (scol+1 <= trow && scol+1 < TT) srow[scol+1] = acc[i][j].y * scale;
        }
    }
}

// =========================================================================
// Kernel 3: causal row softmax in place; zeros for s>t (PV runs unmasked)
// =========================================================================
__global__ void __launch_bounds__(256) softmax_kernel()
{
    const int t = blockIdx.x, hb = blockIdx.y;
    float* row = g_S + ((size_t)hb*TT + t)*TT;
    const int n = t + 1;
    const int tid = threadIdx.x;
    __shared__ float red[256];

    float m = -1e30f;
    for (int i = tid; i < n; i += 256) m = fmaxf(m, row[i]);
    red[tid] = m; __syncthreads();
    for (int s = 128; s > 0; s >>= 1) {
        if (tid < s) red[tid] = fmaxf(red[tid], red[tid+s]);
        __syncthreads();
    }
    const float M = red[0]; __syncthreads();

    float ssum = 0.f;
    for (int i = tid; i < n; i += 256) {
        float e = __expf(row[i] - M);
        row[i] = e;
        ssum += e;
    }
    red[tid] = ssum; __syncthreads();
    for (int s = 128; s > 0; s >>= 1) {
        if (tid < s) red[tid] += red[tid+s];
        __syncthreads();
    }
    const float inv = 1.0f / red[0];
    __syncthreads();
    for (int i = tid; i < n; i += 256) row[i] *= inv;
    for (int i = n + tid; i < TT; i += 256) row[i] = 0.f;
}

// =========================================================================
// Kernel 4: O = P V, k-loop clipped causally, double-buffered
// grid (32 e, 8 t, 16 hb), 256 thr, 128x128 tile
// =========================================================================
__global__ void __launch_bounds__(256) pv_kernel()
{
    const int ex = blockIdx.x, tt = blockIdx.y, hb = blockIdx.z;
    const int t0 = tt*128, e0 = ex*128;
    const int tid = threadIdx.x, ty = tid >> 4, tx = tid & 15;
    __shared__ float Ps[2][16*132], Vs[2][16*132];

    float2 acc[8][4];
    #pragma unroll
    for (int i = 0; i < 8; i++)
        #pragma unroll
        for (int j = 0; j < 4; j++) acc[i][j] = make_float2(0.f, 0.f);

    const float* Pb = g_S + (size_t)hb*TT*TT;
    const float* Vb = g_V + (size_t)hb*TT*EV;
    const int kmax = min(TT, t0 + 128);
    const int NSLAB = (kmax + 15) / 16;
    const int r = tid >> 2, q4 = (tid & 3)*4;
    const int vkr = tid >> 4, vc = (tid & 15)*4;

    float4 vp[2], vv[2];
    // prologue: load slab 0
    #pragma unroll
    for (int pass = 0; pass < 2; pass++) {
        int rr = r + pass*64;
        int tg = t0 + rr, sidx = q4;
        vp[pass] = (tg < TT && sidx < TT)
                 ? *(const float4*)(Pb + (size_t)tg*TT + sidx)
                 : make_float4(0.f,0.f,0.f,0.f);
    }
    {
        int sg = vkr;
        if (sg < TT) {
            const float* vrow = Vb + (size_t)sg*EV + e0;
            vv[0] = *(const float4*)(vrow + vc);
            vv[1] = *(const float4*)(vrow + 64 + vc);
        } else {
            vv[0] = vv[1] = make_float4(0.f,0.f,0.f,0.f);
        }
    }
    #pragma unroll
    for (int pass = 0; pass < 2; pass++) {
        int rr = r + pass*64;
        Ps[0][(q4+0)*132+rr]=vp[pass].x; Ps[0][(q4+1)*132+rr]=vp[pass].y;
        Ps[0][(q4+2)*132+rr]=vp[pass].z; Ps[0][(q4+3)*132+rr]=vp[pass].w;
    }
    *(float4*)(&Vs[0][vkr*132 + vc])      = vv[0];
    *(float4*)(&Vs[0][vkr*132 + 64 + vc]) = vv[1];
    __syncthreads();

    for (int it = 0; it < NSLAB; it++) {
        const int cur = it & 1;
        if (it + 1 < NSLAB) {
            int s0c = (it+1)*16;
            #pragma unroll
            for (int pass = 0; pass < 2; pass++) {
                int rr = r + pass*64;
                int tg = t0 + rr, sidx = s0c + q4;
                vp[pass] = (tg < TT && sidx < TT)
                         ? *(const float4*)(Pb + (size_t)tg*TT + sidx)
                         : make_float4(0.f,0.f,0.f,0.f);
            }
            int sg = s0c + vkr;
            if (sg < TT) {
                const float* vrow = Vb + (size_t)sg*EV + e0;
                vv[0] = *(const float4*)(vrow + vc);
                vv[1] = *(const float4*)(vrow + 64 + vc);
            } else {
                vv[0] = vv[1] = make_float4(0.f,0.f,0.f,0.f);
            }
        }
        const float* psb = Ps[cur];
        const float* vsb = Vs[cur];
        #pragma unroll
        for (int kk = 0; kk < 16; kk++) {
            float4 p0 = *(const float4*)(psb + kk*132 + ty*4);
            float4 p1 = *(const float4*)(psb + kk*132 + 64 + ty*4);
            float4 v0 = *(const float4*)(vsb + kk*132 + tx*4);
            float4 v1 = *(const float4*)(vsb + kk*132 + 64 + tx*4);
            float2 cp[4] = {{v0.x,v0.y},{v0.z,v0.w},{v1.x,v1.y},{v1.z,v1.w}};
            float pv[8] = {p0.x,p0.y,p0.z,p0.w,p1.x,p1.y,p1.z,p1.w};
            #pragma unroll
            for (int i = 0; i < 8; i++) {
                float2 pp = make_float2(pv[i], pv[i]);
                #pragma unroll
                for (int j = 0; j < 4; j++) ffma2(acc[i][j], pp, cp[j]);
            }
        }
        if (it + 1 < NSLAB) {
            const int nxt = cur ^ 1;
            #pragma unroll
            for (int pass = 0; pass < 2; pass++) {
                int rr = r + pass*64;
                Ps[nxt][(q4+0)*132+rr]=vp[pass].x; Ps[nxt][(q4+1)*132+rr]=vp[pass].y;
                Ps[nxt][(q4+2)*132+rr]=vp[pass].z; Ps[nxt][(q4+3)*132+rr]=vp[pass].w;
            }
            *(float4*)(&Vs[nxt][vkr*132 + vc])      = vv[0];
            *(float4*)(&Vs[nxt][vkr*132 + 64 + vc]) = vv[1];
            __syncthreads();
        }
    }

    float* Ob = g_O + (size_t)hb*TT*EV;
    #pragma unroll
    for (int i = 0; i < 8; i++) {
        int trow = t0 + ((i < 4) ? ty*4 + i : 64 + ty*4 + (i-4));
        if (trow >= TT) continue;
        float* orow = Ob + (size_t)trow*EV + e0;
        float4 w0 = make_float4(acc[i][0].x, acc[i][0].y, acc[i][1].x, acc[i][1].y);
        float4 w1 = make_float4(acc[i][2].x, acc[i][2].y, acc[i][3].x, acc[i][3].y);
        *(float4*)(orow + tx*4) = w0;
        *(float4*)(orow + 64 + tx*4) = w1;
    }
}

// =========================================================================
// Kernel 5: projection GEMM + bias + PReLU + LayerNorm(all) + residual
// grid (T, B), 256 threads
// =========================================================================
#define SMEM_E (2*128*132*4)
__global__ void __launch_bounds__(256, 1) proj_kernel(
    const float* __restrict__ x,
    const float* __restrict__ Wp, const float* __restrict__ bp,
    const float* __restrict__ ap, const float* __restrict__ gp,
    const float* __restrict__ bep, float* __restrict__ out)
{
    const int t = blockIdx.x, b = blockIdx.y;
    const int tid = threadIdx.x, ty = tid >> 4, tx = tid & 15;
    extern __shared__ float sm[];
    float* Xs  = sm;             // [128 c][132]
    float* Wst = sm + 128*132;   // [128 c][132]
    __shared__ float ssum[256], ssq[256], stats[2];

    // gather O tile: channel c = h*32+v  <-  g_O[h*B+b][t][v*128+f]
    {
        int c = tid >> 1, hh = (tid & 1)*64;
        int h = c >> 5, vrow = c & 31;
        const float4* src = (const float4*)(g_O + (((size_t)(h*BB + b))*TT + t)*EV + vrow*FF + hh);
        float4* dst = (float4*)(Xs + c*132 + hh);
        #pragma unroll
        for (int i = 0; i < 16; i++) dst[i] = src[i];
    }
    // stage Wp transposed
    {
        int o = tid & 127, ch = tid >> 7;
        const float4* wr = (const float4*)(Wp + o*128) + ch*16;
        #pragma unroll
        for (int i = 0; i < 16; i++) {
            float4 v = wr[i];
            int c = (ch*16 + i)*4;
            Wst[(c+0)*132 + o] = v.x;
            Wst[(c+1)*132 + o] = v.y;
            Wst[(c+2)*132 + o] = v.z;
            Wst[(c+3)*132 + o] = v.w;
        }
    }
    __syncthreads();

    // microtile: 8 oc (ty*4..+3, 64+ty*4..+3; 4 pairs) x 8 f
    float2 acc[4][8];
    #pragma unroll
    for (int p = 0; p < 4; p++)
        #pragma unroll
        for (int f = 0; f < 8; f++) acc[p][f] = make_float2(0.f, 0.f);

    for (int c = 0; c < 128; c++) {
        float4 w0 = *(const float4*)(Wst + c*132 + ty*4);
        float4 w1 = *(const float4*)(Wst + c*132 + 64 + ty*4);
        float4 xa = *(const float4*)(Xs + c*132 + tx*4);
        float4 xb = *(const float4*)(Xs + c*132 + 64 + tx*4);
        float2 wp2[4] = {{w0.x,w0.y},{w0.z,w0.w},{w1.x,w1.y},{w1.z,w1.w}};
        float xv[8] = {xa.x,xa.y,xa.z,xa.w,xb.x,xb.y,xb.z,xb.w};
        #pragma unroll
        for (int f = 0; f < 8; f++) {
            float2 xx = make_float2(xv[f], xv[f]);
            #pragma unroll
            for (int p = 0; p < 4; p++) ffma2(acc[p][f], wp2[p], xx);
        }
    }

    const float alpha = ap[0];
    float s1 = 0.f, s2 = 0.f;
    #pragma unroll
    for (int p = 0; p < 4; p++) {
        int o0 = (p < 2) ? ty*4 + 2*p : 64 + ty*4 + 2*(p-2);
        float b0 = bp[o0], b1 = bp[o0+1];
        #pragma unroll
        for (int f = 0; f < 8; f++) {
            float vx = acc[p][f].x + b0; vx = vx >= 0.f ? vx : alpha*vx;
            float vy = acc[p][f].y + b1; vy = vy >= 0.f ? vy : alpha*vy;
            acc[p][f].x = vx; acc[p][f].y = vy;
            s1 += vx + vy; s2 += vx*vx + vy*vy;
        }
    }
    ssum[tid] = s1; ssq[tid] = s2;
    __syncthreads();
    for (int s = 128; s > 0; s >>= 1) {
        if (tid < s) { ssum[tid] += ssum[tid+s]; ssq[tid] += ssq[tid+s]; }
        __syncthreads();
    }
    if (tid == 0) {
        float mu  = ssum[0] * (1.f/16384.f);
        float var = ssq[0]  * (1.f/16384.f) - mu*mu;
        stats[0] = mu;
        stats[1] = rsqrtf(var + EPSL);
    }
    __syncthreads();
    const float mu = stats[0], rs = stats[1];

    #pragma unroll
    for (int p = 0; p < 4; p++) {
        #pragma unroll
        for (int lane = 0; lane < 2; lane++) {
            int o = ((p < 2) ? ty*4 + 2*p : 64 + ty*4 + 2*(p-2)) + lane;
            const float* grow  = gp  + o*FF;
            const float* berow = bep + o*FF;
            const float* xrow  = x   + (((size_t)b*CC + o)*TT + t)*FF;
            float*       orow  = out + (((size_t)b*CC + o)*TT + t)*FF;
            #pragma unroll
            for (int half = 0; half < 2; half++) {
                int fc = half*64 + tx*4;
                float4 g4  = *(const float4*)(grow + fc);
                float4 be4 = *(const float4*)(berow + fc);
                float4 x4  = *(const float4*)(xrow + fc);
                float v0 = lane ? acc[p][half*4+0].y : acc[p][half*4+0].x;
                float v1 = lane ? acc[p][half*4+1].y : acc[p][half*4+1].x;
                float v2 = lane ? acc[p][half*4+2].y : acc[p][half*4+2].x;
                float v3 = lane ? acc[p][half*4+3].y : acc[p][half*4+3].x;
                float4 o4;
                o4.x = (v0 - mu)*rs*g4.x + be4.x + x4.x;
                o4.y = (v1 - mu)*rs*g4.y + be4.y + x4.y;
                o4.z = (v2 - mu)*rs*g4.z + be4.z + x4.z;
                o4.w = (v3 - mu)*rs*g4.w + be4.w + x4.w;
                *(float4*)(orow + fc) = o4;
            }
        }
    }
}

// =========================================================================
extern "C" void kernel_launch(void* const* d_in, const int* in_sizes, int n_in,
                              void* d_out, int out_size) {
    (void)in_sizes; (void)n_in; (void)out_size;
    const float* x   = (const float*)d_in[0];
    const float* Wq  = (const float*)d_in[1];
    const float* bq  = (const float*)d_in[2];
    const float* aq  = (const float*)d_in[3];
    const float* gq  = (const float*)d_in[4];
    const float* beq = (const float*)d_in[5];
    const float* Wk  = (const float*)d_in[6];
    const float* bk  = (const float*)d_in[7];
    const float* ak  = (const float*)d_in[8];
    const float* gk  = (const float*)d_in[9];
    const float* bek = (const float*)d_in[10];
    const float* Wv  = (const float*)d_in[11];
    const float* bv  = (const float*)d_in[12];
    const float* av  = (const float*)d_in[13];
    const float* gv  = (const float*)d_in[14];
    const float* bev = (const float*)d_in[15];
    const float* Wp  = (const float*)d_in[16];
    const float* bp  = (const float*)d_in[17];
    const float* ap  = (const float*)d_in[18];
    const float* gp  = (const float*)d_in[19];
    const float* bep = (const float*)d_in[20];
    float* out = (float*)d_out;

    cudaFuncSetAttribute(qkv_kernel,  cudaFuncAttributeMaxDynamicSharedMemorySize, SMEM_A);
    cudaFuncSetAttribute(proj_kernel, cudaFuncAttributeMaxDynamicSharedMemorySize, SMEM_E);

    qkv_kernel<<<dim3(TT, BB), 256, SMEM_A>>>(x, Wq, bq, aq, gq, beq,
                                              Wk, bk, ak, gk, bek,
                                              Wv, bv, av, gv, bev);
    score_kernel<<<dim3(36, 1, 16), 256>>>();
    softmax_kernel<<<dim3(TT, 16), 256>>>();
    pv_kernel<<<dim3(32, 8, 16), 256>>>();
    proj_kernel<<<dim3(TT, BB), 256, SMEM_E>>>(x, Wp, bp, ap, gp, bep, out);
}

// round 8
// speedup vs baseline: 1.4293x; 1.4293x over previous
#include <cuda_runtime.h>
#include <math.h>

#define BB   4
#define CC   128
#define TT   1000
#define FF   128
#define NHD  4
#define HID  16
#define VD   32
#define EQ   2048
#define EV   4096
#define EPSL 1e-5f

// ---------------- scratch (device globals; no allocation) ----------------
__device__ float g_Q[(size_t)NHD*BB*TT*EQ];   // [hb][t][e]
__device__ float g_K[(size_t)NHD*BB*TT*EQ];
__device__ float g_V[(size_t)NHD*BB*TT*EV];
__device__ float g_S[(size_t)NHD*BB*TT*TT];   // scores -> probs
__device__ float g_O[(size_t)NHD*BB*TT*EV];   // attention output

// packed fp32x2 FMA: d = a*b + d  (FFMA2: 2x fp32 throughput, PTX-only path)
__device__ __forceinline__ void ffma2(float2 &d, float2 a, float2 b) {
    asm("fma.rn.f32x2 %0, %1, %2, %0;"
        : "+l"(reinterpret_cast<unsigned long long&>(d))
        : "l"(reinterpret_cast<unsigned long long&>(a)),
          "l"(reinterpret_cast<unsigned long long&>(b)));
}

// round f32 -> tf32 (rna) so tensor-core truncation is unbiased
__device__ __forceinline__ float tf32r(float x) {
    unsigned u;
    asm("cvt.rna.tf32.f32 %0, %1;" : "=r"(u) : "f"(x));
    return __uint_as_float(u);
}

// m16n8k8 tf32 MMA, D += A*B  (A row-major 16x8, B col-major 8x8, f32 accum)
__device__ __forceinline__ void mma8(float d[4], const float a[4], const float b[2]) {
    asm("mma.sync.aligned.m16n8k8.row.col.f32.tf32.tf32.f32 "
        "{%0,%1,%2,%3}, {%4,%5,%6,%7}, {%8,%9}, {%0,%1,%2,%3};"
        : "+f"(d[0]), "+f"(d[1]), "+f"(d[2]), "+f"(d[3])
        : "r"(__float_as_uint(a[0])), "r"(__float_as_uint(a[1])),
          "r"(__float_as_uint(a[2])), "r"(__float_as_uint(a[3])),
          "r"(__float_as_uint(b[0])), "r"(__float_as_uint(b[1])));
}

// =========================================================================
// Kernel 1: fused QKV 1x1-conv GEMM + bias + PReLU + group LayerNorm
// grid (T, B), 256 threads. Out channels: [Q 0..63 | K 64..127 | V 128..255]
// =========================================================================
#define SMEM_A ((128*132 + 128*256)*4)
__global__ void __launch_bounds__(256, 1) qkv_kernel(
    const float* __restrict__ x,
    const float* __restrict__ Wq, const float* __restrict__ bq,
    const float* __restrict__ aq, const float* __restrict__ gq, const float* __restrict__ beq,
    const float* __restrict__ Wk, const float* __restrict__ bk,
    const float* __restrict__ ak, const float* __restrict__ gk, const float* __restrict__ bek,
    const float* __restrict__ Wv, const float* __restrict__ bv,
    const float* __restrict__ av, const float* __restrict__ gv, const float* __restrict__ bev)
{
    const int t = blockIdx.x, b = blockIdx.y;
    const int tid = threadIdx.x, ty = tid >> 4, tx = tid & 15;
    extern __shared__ float sm[];
    float* Xs = sm;             // [128 c][132 f-padded]
    float* Ws = sm + 128*132;   // [128 c][256 oc]
    __shared__ float ssum[256], ssq[256], gmu[12], grs[12];

    // stage X[b, :, t, :]
    {
        int c = tid >> 1, hh = (tid & 1) * 64;
        const float4* src = (const float4*)(x + (((size_t)b*CC + c)*TT + t)*FF + hh);
        float4* dst = (float4*)(Xs + c*132 + hh);
        #pragma unroll
        for (int i = 0; i < 16; i++) dst[i] = src[i];
    }
    // stage combined W, c-major
    {
        const float* wrow = (tid < 64)  ? (Wq + tid*CC)
                          : (tid < 128) ? (Wk + (tid-64)*CC)
                          :               (Wv + (tid-128)*CC);
        const float4* w4 = (const float4*)wrow;
        #pragma unroll
        for (int c4 = 0; c4 < 32; c4++) {
            float4 v = w4[c4];
            int c = c4*4;
            Ws[(c+0)*256 + tid] = v.x;
            Ws[(c+1)*256 + tid] = v.y;
            Ws[(c+2)*256 + tid] = v.z;
            Ws[(c+3)*256 + tid] = v.w;
        }
    }
    __syncthreads();

    // microtile: 16 oc (ty*16..+15, as 8 pairs) x 8 f (tx*4..+3, 64+tx*4..+3)
    float2 acc[8][8];
    #pragma unroll
    for (int p = 0; p < 8; p++)
        #pragma unroll
        for (int f = 0; f < 8; f++) acc[p][f] = make_float2(0.f, 0.f);

    for (int c = 0; c < 128; c++) {
        const float* xr = Xs + c*132;
        float4 xa = *(const float4*)(xr + tx*4);
        float4 xb = *(const float4*)(xr + 64 + tx*4);
        const float4* wr = (const float4*)(Ws + c*256) + ty*4;
        float4 w0 = wr[0], w1 = wr[1], w2 = wr[2], w3 = wr[3];
        float2 wp2[8] = {{w0.x,w0.y},{w0.z,w0.w},{w1.x,w1.y},{w1.z,w1.w},
                         {w2.x,w2.y},{w2.z,w2.w},{w3.x,w3.y},{w3.z,w3.w}};
        float xv[8] = {xa.x,xa.y,xa.z,xa.w,xb.x,xb.y,xb.z,xb.w};
        #pragma unroll
        for (int f = 0; f < 8; f++) {
            float2 xx = make_float2(xv[f], xv[f]);
            #pragma unroll
            for (int p = 0; p < 8; p++) ffma2(acc[p][f], wp2[p], xx);
        }
    }

    // bias + PReLU + local sums
    float alpha = (ty < 4) ? aq[ty] : (ty < 8) ? ak[ty-4] : av[(ty-8)>>1];
    int grp = (ty < 8) ? ty : 8 + ((ty-8)>>1);
    float s1 = 0.f, s2 = 0.f;
    #pragma unroll
    for (int p = 0; p < 8; p++) {
        int occ = ty*16 + 2*p;
        float b0 = (occ < 64) ? bq[occ]   : (occ < 128) ? bk[occ-64] : bv[occ-128];
        float b1 = (occ < 64) ? bq[occ+1] : (occ < 128) ? bk[occ-63] : bv[occ-127];
        #pragma unroll
        for (int f = 0; f < 8; f++) {
            float vx = acc[p][f].x + b0; vx = vx >= 0.f ? vx : alpha*vx;
            float vy = acc[p][f].y + b1; vy = vy >= 0.f ? vy : alpha*vy;
            acc[p][f].x = vx; acc[p][f].y = vy;
            s1 += vx + vy; s2 += vx*vx + vy*vy;
        }
    }
    ssum[tid] = s1; ssq[tid] = s2;
    __syncthreads();
    // 12 LN groups map to contiguous tid ranges
    if (tid < 12) {
        int st = (tid < 8) ? tid*16 : 128 + (tid-8)*32;
        int n  = (tid < 8) ? 16 : 32;
        float a = 0.f, q = 0.f;
        for (int i = 0; i < n; i++) { a += ssum[st+i]; q += ssq[st+i]; }
        float N = (tid < 8) ? 2048.f : 4096.f;
        float mu = a / N;
        float var = q / N - mu*mu;
        gmu[tid] = mu;
        grs[tid] = rsqrtf(var + EPSL);
    }
    __syncthreads();
    float mu = gmu[grp], rs = grs[grp];

    // normalize + affine, write in attention layout [hb][t][e]
    #pragma unroll
    for (int p = 0; p < 8; p++) {
        #pragma unroll
        for (int lane = 0; lane < 2; lane++) {
            int occ = ty*16 + 2*p + lane;
            const float* grow; const float* berow; float* dst;
            if (occ < 64) {
                grow = gq + occ*FF; berow = beq + occ*FF;
                int h = occ >> 4, r = occ & 15;
                dst = g_Q + (((size_t)(h*BB + b))*TT + t)*EQ + r*FF;
            } else if (occ < 128) {
                int o2 = occ - 64;
                grow = gk + o2*FF; berow = bek + o2*FF;
                int h = o2 >> 4, r = o2 & 15;
                dst = g_K + (((size_t)(h*BB + b))*TT + t)*EQ + r*FF;
            } else {
                int o2 = occ - 128;
                grow = gv + o2*FF; berow = bev + o2*FF;
                int h = o2 >> 5, r = o2 & 31;
                dst = g_V + (((size_t)(h*BB + b))*TT + t)*EV + r*FF;
            }
            #pragma unroll
            for (int half = 0; half < 2; half++) {
                int fc = half*64 + tx*4;
                float4 g4  = *(const float4*)(grow + fc);
                float4 be4 = *(const float4*)(berow + fc);
                float v0 = lane ? acc[p][half*4+0].y : acc[p][half*4+0].x;
                float v1 = lane ? acc[p][half*4+1].y : acc[p][half*4+1].x;
                float v2 = lane ? acc[p][half*4+2].y : acc[p][half*4+2].x;
                float v3 = lane ? acc[p][half*4+3].y : acc[p][half*4+3].x;
                float4 o;
                o.x = (v0 - mu)*rs*g4.x + be4.x;
                o.y = (v1 - mu)*rs*g4.y + be4.y;
                o.z = (v2 - mu)*rs*g4.z + be4.z;
                o.w = (v3 - mu)*rs*g4.w + be4.w;
                *(float4*)(dst + fc) = o;
            }
        }
    }
}

// =========================================================================
// Kernel 2: S = Q K^T * scale, lower-tri tiles, double-buffered, tf32 MMA
// grid (36, 1, 16), 256 thr (8 warps, 2x4 warp grid), 128x128 tile, k=2048
// =========================================================================
__global__ void __launch_bounds__(256) score_kernel()
{
    // map linear tile id -> (tt, ss) with ss <= tt
    int idx = blockIdx.x;
    int tt = (int)((sqrtf(8.f*idx + 1.f) - 1.f) * 0.5f);
    while ((tt+1)*(tt+2)/2 <= idx) tt++;
    while (tt*(tt+1)/2 > idx) tt--;
    const int ss = idx - tt*(tt+1)/2;
    const int hb = blockIdx.z;
    const int t0 = tt*128, s0 = ss*128;
    const int tid = threadIdx.x;
    const int wid = tid >> 5, lane = tid & 31;
    const int g = lane >> 2, t4 = lane & 3;
    const int mw = (wid >> 2) * 64;   // warp m (t-row) offset: 0 or 64
    const int nw = (wid & 3) * 32;    // warp n (s-col) offset: 0..96
    __shared__ float Qs[2][16*132], Ks[2][16*132];

    float acc[4][4][4];
    #pragma unroll
    for (int mi = 0; mi < 4; mi++)
        #pragma unroll
        for (int ni = 0; ni < 4; ni++)
            #pragma unroll
            for (int rr2 = 0; rr2 < 4; rr2++) acc[mi][ni][rr2] = 0.f;

    const float* Qb = g_Q + (size_t)hb*TT*EQ;
    const float* Kb = g_K + (size_t)hb*TT*EQ;
    const int r = tid >> 2, q4 = (tid & 3)*4;

    float4 vq[2], vk[2];
    // prologue: load slab 0
    #pragma unroll
    for (int pass = 0; pass < 2; pass++) {
        int rr = r + pass*64;
        int tg = t0 + rr, sg = s0 + rr;
        vq[pass] = (tg < TT) ? *(const float4*)(Qb + (size_t)tg*EQ + q4)
                             : make_float4(0.f,0.f,0.f,0.f);
        vk[pass] = (sg < TT) ? *(const float4*)(Kb + (size_t)sg*EQ + q4)
                             : make_float4(0.f,0.f,0.f,0.f);
    }
    #pragma unroll
    for (int pass = 0; pass < 2; pass++) {
        int rr = r + pass*64;
        Qs[0][(q4+0)*132+rr]=tf32r(vq[pass].x); Qs[0][(q4+1)*132+rr]=tf32r(vq[pass].y);
        Qs[0][(q4+2)*132+rr]=tf32r(vq[pass].z); Qs[0][(q4+3)*132+rr]=tf32r(vq[pass].w);
        Ks[0][(q4+0)*132+rr]=tf32r(vk[pass].x); Ks[0][(q4+1)*132+rr]=tf32r(vk[pass].y);
        Ks[0][(q4+2)*132+rr]=tf32r(vk[pass].z); Ks[0][(q4+3)*132+rr]=tf32r(vk[pass].w);
    }
    __syncthreads();

    const int NSLAB = EQ/16;  // 128
    for (int it = 0; it < NSLAB; it++) {
        const int cur = it & 1;
        if (it + 1 < NSLAB) {
            int e0 = (it+1)*16;
            #pragma unroll
            for (int pass = 0; pass < 2; pass++) {
                int rr = r + pass*64;
                int tg = t0 + rr, sg = s0 + rr;
                vq[pass] = (tg < TT) ? *(const float4*)(Qb + (size_t)tg*EQ + e0 + q4)
                                     : make_float4(0.f,0.f,0.f,0.f);
                vk[pass] = (sg < TT) ? *(const float4*)(Kb + (size_t)sg*EQ + e0 + q4)
                                     : make_float4(0.f,0.f,0.f,0.f);
            }
        }
        const float* qsb = Qs[cur];
        const float* ksb = Ks[cur];
        #pragma unroll
        for (int kb = 0; kb < 16; kb += 8) {
            float a[4][4], bfr[4][2];
            #pragma unroll
            for (int mi = 0; mi < 4; mi++) {
                int m = mw + mi*16 + g;
                a[mi][0] = qsb[(kb+t4)*132 + m];
                a[mi][1] = qsb[(kb+t4)*132 + m + 8];
                a[mi][2] = qsb[(kb+t4+4)*132 + m];
                a[mi][3] = qsb[(kb+t4+4)*132 + m + 8];
            }
            #pragma unroll
            for (int ni = 0; ni < 4; ni++) {
                int n = nw + ni*8 + g;
                bfr[ni][0] = ksb[(kb+t4)*132 + n];
                bfr[ni][1] = ksb[(kb+t4+4)*132 + n];
            }
            #pragma unroll
            for (int mi = 0; mi < 4; mi++)
                #pragma unroll
                for (int ni = 0; ni < 4; ni++)
                    mma8(acc[mi][ni], a[mi], bfr[ni]);
        }
        if (it + 1 < NSLAB) {
            const int nxt = cur ^ 1;
            #pragma unroll
            for (int pass = 0; pass < 2; pass++) {
                int rr = r + pass*64;
                Qs[nxt][(q4+0)*132+rr]=tf32r(vq[pass].x); Qs[nxt][(q4+1)*132+rr]=tf32r(vq[pass].y);
                Qs[nxt][(q4+2)*132+rr]=tf32r(vq[pass].z); Qs[nxt][(q4+3)*132+rr]=tf32r(vq[pass].w);
                Ks[nxt][(q4+0)*132+rr]=tf32r(vk[pass].x); Ks[nxt][(q4+1)*132+rr]=tf32r(vk[pass].y);
                Ks[nxt][(q4+2)*132+rr]=tf32r(vk[pass].z); Ks[nxt][(q4+3)*132+rr]=tf32r(vk[pass].w);
            }
            __syncthreads();
        }
    }

    const float scale = 0.022097086912079608f;  // 1/sqrt(2048)
    float* Sb = g_S + (size_t)hb*TT*TT;
    #pragma unroll
    for (int mi = 0; mi < 4; mi++) {
        #pragma unroll
        for (int ni = 0; ni < 4; ni++) {
            int tr0 = t0 + mw + mi*16 + g;
            int nc  = s0 + nw + ni*8 + t4*2;
            const float* d = acc[mi][ni];
            if (tr0 < TT) {
                float* row = Sb + (size_t)tr0*TT;
                if (nc   <= tr0) row[nc]   = d[0]*scale;
                if (nc+1 <= tr0) row[nc+1] = d[1]*scale;
            }
            int tr1 = tr0 + 8;
            if (tr1 < TT) {
                float* row = Sb + (size_t)tr1*TT;
                if (nc   <= tr1) row[nc]   = d[2]*scale;
                if (nc+1 <= tr1) row[nc+1] = d[3]*scale;
            }
        }
    }
}

// =========================================================================
// Kernel 3: causal row softmax in place; zeros for s>t (PV runs unmasked)
// =========================================================================
__global__ void __launch_bounds__(256) softmax_kernel()
{
    const int t = blockIdx.x, hb = blockIdx.y;
    float* row = g_S + ((size_t)hb*TT + t)*TT;
    const int n = t + 1;
    const int tid = threadIdx.x;
    __shared__ float red[256];

    float m = -1e30f;
    for (int i = tid; i < n; i += 256) m = fmaxf(m, row[i]);
    red[tid] = m; __syncthreads();
    for (int s = 128; s > 0; s >>= 1) {
        if (tid < s) red[tid] = fmaxf(red[tid], red[tid+s]);
        __syncthreads();
    }
    const float M = red[0]; __syncthreads();

    float ssum = 0.f;
    for (int i = tid; i < n; i += 256) {
        float e = __expf(row[i] - M);
        row[i] = e;
        ssum += e;
    }
    red[tid] = ssum; __syncthreads();
    for (int s = 128; s > 0; s >>= 1) {
        if (tid < s) red[tid] += red[tid+s];
        __syncthreads();
    }
    const float inv = 1.0f / red[0];
    __syncthreads();
    for (int i = tid; i < n; i += 256) row[i] *= inv;
    for (int i = n + tid; i < TT; i += 256) row[i] = 0.f;
}

// =========================================================================
// Kernel 4: O = P V, causal k-clip, double-buffered, tf32 MMA
// grid (32 e, 8 t, 16 hb), 256 thr (2x4 warp grid), 128x128 tile
// =========================================================================
__global__ void __launch_bounds__(256) pv_kernel()
{
    const int ex = blockIdx.x, tt = blockIdx.y, hb = blockIdx.z;
    const int t0 = tt*128, e0 = ex*128;
    const int tid = threadIdx.x;
    const int wid = tid >> 5, lane = tid & 31;
    const int g = lane >> 2, t4 = lane & 3;
    const int mw = (wid >> 2) * 64;   // t-row offset within tile
    const int nw = (wid & 3) * 32;    // e-col offset within tile
    __shared__ float Ps[2][16*132], Vs[2][16*132];

    float acc[4][4][4];
    #pragma unroll
    for (int mi = 0; mi < 4; mi++)
        #pragma unroll
        for (int ni = 0; ni < 4; ni++)
            #pragma unroll
            for (int rr2 = 0; rr2 < 4; rr2++) acc[mi][ni][rr2] = 0.f;

    const float* Pb = g_S + (size_t)hb*TT*TT;
    const float* Vb = g_V + (size_t)hb*TT*EV;
    const int kmax = min(TT, t0 + 128);
    const int NSLAB = (kmax + 15) / 16;
    const int r = tid >> 2, q4 = (tid & 3)*4;
    const int vkr = tid >> 4, vc = (tid & 15)*4;

    float4 vp[2], vv[2];
    // prologue: load slab 0
    #pragma unroll
    for (int pass = 0; pass < 2; pass++) {
        int rr = r + pass*64;
        int tg = t0 + rr, sidx = q4;
        vp[pass] = (tg < TT && sidx < TT)
                 ? *(const float4*)(Pb + (size_t)tg*TT + sidx)
                 : make_float4(0.f,0.f,0.f,0.f);
    }
    {
        int sg = vkr;
        if (sg < TT) {
            const float* vrow = Vb + (size_t)sg*EV + e0;
            vv[0] = *(const float4*)(vrow + vc);
            vv[1] = *(const float4*)(vrow + 64 + vc);
        } else {
            vv[0] = vv[1] = make_float4(0.f,0.f,0.f,0.f);
        }
    }
    #pragma unroll
    for (int pass = 0; pass < 2; pass++) {
        int rr = r + pass*64;
        Ps[0][(q4+0)*132+rr]=tf32r(vp[pass].x); Ps[0][(q4+1)*132+rr]=tf32r(vp[pass].y);
        Ps[0][(q4+2)*132+rr]=tf32r(vp[pass].z); Ps[0][(q4+3)*132+rr]=tf32r(vp[pass].w);
    }
    Vs[0][vkr*132 + vc+0]      = tf32r(vv[0].x);
    Vs[0][vkr*132 + vc+1]      = tf32r(vv[0].y);
    Vs[0][vkr*132 + vc+2]      = tf32r(vv[0].z);
    Vs[0][vkr*132 + vc+3]      = tf32r(vv[0].w);
    Vs[0][vkr*132 + 64 + vc+0] = tf32r(vv[1].x);
    Vs[0][vkr*132 + 64 + vc+1] = tf32r(vv[1].y);
    Vs[0][vkr*132 + 64 + vc+2] = tf32r(vv[1].z);
    Vs[0][vkr*132 + 64 + vc+3] = tf32r(vv[1].w);
    __syncthreads();

    for (int it = 0; it < NSLAB; it++) {
        const int cur = it & 1;
        if (it + 1 < NSLAB) {
            int s0c = (it+1)*16;
            #pragma unroll
            for (int pass = 0; pass < 2; pass++) {
                int rr = r + pass*64;
                int tg = t0 + rr, sidx = s0c + q4;
                vp[pass] = (tg < TT && sidx < TT)
                         ? *(const float4*)(Pb + (size_t)tg*TT + sidx)
                         : make_float4(0.f,0.f,0.f,0.f);
            }
            int sg = s0c + vkr;
            if (sg < TT) {
                const float* vrow = Vb + (size_t)sg*EV + e0;
                vv[0] = *(const float4*)(vrow + vc);
                vv[1] = *(const float4*)(vrow + 64 + vc);
            } else {
                vv[0] = vv[1] = make_float4(0.f,0.f,0.f,0.f);
            }
        }
        const float* psb = Ps[cur];
        const float* vsb = Vs[cur];
        #pragma unroll
        for (int kb = 0; kb < 16; kb += 8) {
            float a[4][4], bfr[4][2];
            #pragma unroll
            for (int mi = 0; mi < 4; mi++) {
                int m = mw + mi*16 + g;
                a[mi][0] = psb[(kb+t4)*132 + m];
                a[mi][1] = psb[(kb+t4)*132 + m + 8];
                a[mi][2] = psb[(kb+t4+4)*132 + m];
                a[mi][3] = psb[(kb+t4+4)*132 + m + 8];
            }
            #pragma unroll
            for (int ni = 0; ni < 4; ni++) {
                int n = nw + ni*8 + g;
                bfr[ni][0] = vsb[(kb+t4)*132 + n];
                bfr[ni][1] = vsb[(kb+t4+4)*132 + n];
            }
            #pragma unroll
            for (int mi = 0; mi < 4; mi++)
                #pragma unroll
                for (int ni = 0; ni < 4; ni++)
                    mma8(acc[mi][ni], a[mi], bfr[ni]);
        }
        if (it + 1 < NSLAB) {
            const int nxt = cur ^ 1;
            #pragma unroll
            for (int pass = 0; pass < 2; pass++) {
                int rr = r + pass*64;
                Ps[nxt][(q4+0)*132+rr]=tf32r(vp[pass].x); Ps[nxt][(q4+1)*132+rr]=tf32r(vp[pass].y);
                Ps[nxt][(q4+2)*132+rr]=tf32r(vp[pass].z); Ps[nxt][(q4+3)*132+rr]=tf32r(vp[pass].w);
            }
            Vs[nxt][vkr*132 + vc+0]      = tf32r(vv[0].x);
            Vs[nxt][vkr*132 + vc+1]      = tf32r(vv[0].y);
            Vs[nxt][vkr*132 + vc+2]      = tf32r(vv[0].z);
            Vs[nxt][vkr*132 + vc+3]      = tf32r(vv[0].w);
            Vs[nxt][vkr*132 + 64 + vc+0] = tf32r(vv[1].x);
            Vs[nxt][vkr*132 + 64 + vc+1] = tf32r(vv[1].y);
            Vs[nxt][vkr*132 + 64 + vc+2] = tf32r(vv[1].z);
            Vs[nxt][vkr*132 + 64 + vc+3] = tf32r(vv[1].w);
            __syncthreads();
        }
    }

    float* Ob = g_O + (size_t)hb*TT*EV;
    #pragma unroll
    for (int mi = 0; mi < 4; mi++) {
        #pragma unroll
        for (int ni = 0; ni < 4; ni++) {
            int tr0 = t0 + mw + mi*16 + g;
            int nc  = nw + ni*8 + t4*2;
            const float* d = acc[mi][ni];
            if (tr0 < TT) {
                float2* p2 = (float2*)(Ob + (size_t)tr0*EV + e0 + nc);
                *p2 = make_float2(d[0], d[1]);
            }
            int tr1 = tr0 + 8;
            if (tr1 < TT) {
                float2* p2 = (float2*)(Ob + (size_t)tr1*EV + e0 + nc);
                *p2 = make_float2(d[2], d[3]);
            }
        }
    }
}

// =========================================================================
// Kernel 5: projection GEMM + bias + PReLU + LayerNorm(all) + residual
// grid (T, B), 256 threads
// =========================================================================
#define SMEM_E (2*128*132*4)
__global__ void __launch_bounds__(256, 1) proj_kernel(
    const float* __restrict__ x,
    const float* __restrict__ Wp, const float* __restrict__ bp,
    const float* __restrict__ ap, const float* __restrict__ gp,
    const float* __restrict__ bep, float* __restrict__ out)
{
    const int t = blockIdx.x, b = blockIdx.y;
    const int tid = threadIdx.x, ty = tid >> 4, tx = tid & 15;
    extern __shared__ float sm[];
    float* Xs  = sm;             // [128 c][132]
    float* Wst = sm + 128*132;   // [128 c][132]
    __shared__ float ssum[256], ssq[256], stats[2];

    // gather O tile: channel c = h*32+v  <-  g_O[h*B+b][t][v*128+f]
    {
        int c = tid >> 1, hh = (tid & 1)*64;
        int h = c >> 5, vrow = c & 31;
        const float4* src = (const float4*)(g_O + (((size_t)(h*BB + b))*TT + t)*EV + vrow*FF + hh);
        float4* dst = (float4*)(Xs + c*132 + hh);
        #pragma unroll
        for (int i = 0; i < 16; i++) dst[i] = src[i];
    }
    // stage Wp transposed
    {
        int o = tid & 127, ch = tid >> 7;
        const float4* wr = (const float4*)(Wp + o*128) + ch*16;
        #pragma unroll
        for (int i = 0; i < 16; i++) {
            float4 v = wr[i];
            int c = (ch*16 + i)*4;
            Wst[(c+0)*132 + o] = v.x;
            Wst[(c+1)*132 + o] = v.y;
            Wst[(c+2)*132 + o] = v.z;
            Wst[(c+3)*132 + o] = v.w;
        }
    }
    __syncthreads();

    // microtile: 8 oc (ty*4..+3, 64+ty*4..+3; 4 pairs) x 8 f
    float2 acc[4][8];
    #pragma unroll
    for (int p = 0; p < 4; p++)
        #pragma unroll
        for (int f = 0; f < 8; f++) acc[p][f] = make_float2(0.f, 0.f);

    for (int c = 0; c < 128; c++) {
        float4 w0 = *(const float4*)(Wst + c*132 + ty*4);
        float4 w1 = *(const float4*)(Wst + c*132 + 64 + ty*4);
        float4 xa = *(const float4*)(Xs + c*132 + tx*4);
        float4 xb = *(const float4*)(Xs + c*132 + 64 + tx*4);
        float2 wp2[4] = {{w0.x,w0.y},{w0.z,w0.w},{w1.x,w1.y},{w1.z,w1.w}};
        float xv[8] = {xa.x,xa.y,xa.z,xa.w,xb.x,xb.y,xb.z,xb.w};
        #pragma unroll
        for (int f = 0; f < 8; f++) {
            float2 xx = make_float2(xv[f], xv[f]);
            #pragma unroll
            for (int p = 0; p < 4; p++) ffma2(acc[p][f], wp2[p], xx);
        }
    }

    const float alpha = ap[0];
    float s1 = 0.f, s2 = 0.f;
    #pragma unroll
    for (int p = 0; p < 4; p++) {
        int o0 = (p < 2) ? ty*4 + 2*p : 64 + ty*4 + 2*(p-2);
        float b0 = bp[o0], b1 = bp[o0+1];
        #pragma unroll
        for (int f = 0; f < 8; f++) {
            float vx = acc[p][f].x + b0; vx = vx >= 0.f ? vx : alpha*vx;
            float vy = acc[p][f].y + b1; vy = vy >= 0.f ? vy : alpha*vy;
            acc[p][f].x = vx; acc[p][f].y = vy;
            s1 += vx + vy; s2 += vx*vx + vy*vy;
        }
    }
    ssum[tid] = s1; ssq[tid] = s2;
    __syncthreads();
    for (int s = 128; s > 0; s >>= 1) {
        if (tid < s) { ssum[tid] += ssum[tid+s]; ssq[tid] += ssq[tid+s]; }
        __syncthreads();
    }
    if (tid == 0) {
        float mu  = ssum[0] * (1.f/16384.f);
        float var = ssq[0]  * (1.f/16384.f) - mu*mu;
        stats[0] = mu;
        stats[1] = rsqrtf(var + EPSL);
    }
    __syncthreads();
    const float mu = stats[0], rs = stats[1];

    #pragma unroll
    for (int p = 0; p < 4; p++) {
        #pragma unroll
        for (int lane = 0; lane < 2; lane++) {
            int o = ((p < 2) ? ty*4 + 2*p : 64 + ty*4 + 2*(p-2)) + lane;
            const float* grow  = gp  + o*FF;
            const float* berow = bep + o*FF;
            const float* xrow  = x   + (((size_t)b*CC + o)*TT + t)*FF;
            float*       orow  = out + (((size_t)b*CC + o)*TT + t)*FF;
            #pragma unroll
            for (int half = 0; half < 2; half++) {
                int fc = half*64 + tx*4;
                float4 g4  = *(const float4*)(grow + fc);
                float4 be4 = *(const float4*)(berow + fc);
                float4 x4  = *(const float4*)(xrow + fc);
                float v0 = lane ? acc[p][half*4+0].y : acc[p][half*4+0].x;
                float v1 = lane ? acc[p][half*4+1].y : acc[p][half*4+1].x;
                float v2 = lane ? acc[p][half*4+2].y : acc[p][half*4+2].x;
                float v3 = lane ? acc[p][half*4+3].y : acc[p][half*4+3].x;
                float4 o4;
                o4.x = (v0 - mu)*rs*g4.x + be4.x + x4.x;
                o4.y = (v1 - mu)*rs*g4.y + be4.y + x4.y;
                o4.z = (v2 - mu)*rs*g4.z + be4.z + x4.z;
                o4.w = (v3 - mu)*rs*g4.w + be4.w + x4.w;
                *(float4*)(orow + fc) = o4;
            }
        }
    }
}

// =========================================================================
extern "C" void kernel_launch(void* const* d_in, const int* in_sizes, int n_in,
                              void* d_out, int out_size) {
    (void)in_sizes; (void)n_in; (void)out_size;
    const float* x   = (const float*)d_in[0];
    const float* Wq  = (const float*)d_in[1];
    const float* bq  = (const float*)d_in[2];
    const float* aq  = (const float*)d_in[3];
    const float* gq  = (const float*)d_in[4];
    const float* beq = (const float*)d_in[5];
    const float* Wk  = (const float*)d_in[6];
    const float* bk  = (const float*)d_in[7];
    const float* ak  = (const float*)d_in[8];
    const float* gk  = (const float*)d_in[9];
    const float* bek = (const float*)d_in[10];
    const float* Wv  = (const float*)d_in[11];
    const float* bv  = (const float*)d_in[12];
    const float* av  = (const float*)d_in[13];
    const float* gv  = (const float*)d_in[14];
    const float* bev = (const float*)d_in[15];
    const float* Wp  = (const float*)d_in[16];
    const float* bp  = (const float*)d_in[17];
    const float* ap  = (const float*)d_in[18];
    const float* gp  = (const float*)d_in[19];
    const float* bep = (const float*)d_in[20];
    float* out = (float*)d_out;

    cudaFuncSetAttribute(qkv_kernel,  cudaFuncAttributeMaxDynamicSharedMemorySize, SMEM_A);
    cudaFuncSetAttribute(proj_kernel, cudaFuncAttributeMaxDynamicSharedMemorySize, SMEM_E);

    qkv_kernel<<<dim3(TT, BB), 256, SMEM_A>>>(x, Wq, bq, aq, gq, beq,
                                              Wk, bk, ak, gk, bek,
                                              Wv, bv, av, gv, bev);
    score_kernel<<<dim3(36, 1, 16), 256>>>();
    softmax_kernel<<<dim3(TT, 16), 256>>>();
    pv_kernel<<<dim3(32, 8, 16), 256>>>();
    proj_kernel<<<dim3(TT, BB), 256, SMEM_E>>>(x, Wp, bp, ap, gp, bep, out);
}